// round 10
// baseline (speedup 1.0000x reference)
#include <cuda_runtime.h>

#define NN 1024
#define NMASK 1023
#define NH 512
#define TC 32          // subband cols per block
#define TR 32          // subband rows per block
#define HROWS 70       // halo rows: 2*32 + 6
#define TSTRIDE 76     // intermediate row stride (bank-shift 12 mod 32: conflict-free STS)

// lo[j] = w[7-j] (index reversal, free); hi[j] = (j odd) ? w[j] : -w[j]
// (negation folded into the FFMA operand modifier, free in SASS).
#define FMA_LO(v, j, s) (s) = fmaf((v), w[7 - (j)], (s))
#define FMA_HI(v, j, s) (s) = ((j) & 1) ? fmaf((v), w[(j)], (s)) \
                                        : fmaf((v), -w[(j)], (s))

__global__ __launch_bounds__(256, 6)
void wav2d_kernel(const float* __restrict__ x,
                  const float* __restrict__ bmt,
                  float* __restrict__ out)
{
    __shared__ float tmp[HROWS * TSTRIDE];   // 21280 B

    const int tid = threadIdx.x;
    const int b  = blockIdx.z;
    const int r0 = blockIdx.y * TR;
    const int c0 = blockIdx.x * TC;

    float w[8];
    #pragma unroll
    for (int j = 0; j < 8; ++j) w[j] = __ldg(&bmt[j]);

    const float* xb = x + (size_t)b * NN * NN;
    const int gr0  = 2 * r0 - 3;   // first halo row (wrapped)
    const int gc0a = 2 * c0 - 4;   // first halo col, 16B-aligned when in-bounds

    // ---- Phase 1: horizontal filter, global -> regs -> smem ----
    // Task t (of 70*4=280): row = t>>2, oct o = t&3 -> output cols 8o..8o+7.
    // Needs 23 input floats at local cols 16o .. 16o+22 (6 float4, f[1..22]).
    const bool xint = (blockIdx.x >= 1) & (blockIdx.x <= 14);
    #pragma unroll
    for (int it = 0; it < 2; ++it) {
        int task = tid + it * 256;
        if (task < HROWS * 4) {
            int row = task >> 2;
            int o   = task & 3;
            int gr  = (gr0 + row) & NMASK;
            const float* rowp = xb + (size_t)gr * NN;

            float f[24];
            if (xint) {
                const float4* p = (const float4*)(rowp + gc0a) + 4 * o;
                #pragma unroll
                for (int v = 0; v < 6; ++v) {
                    float4 t4 = __ldg(p + v);
                    f[4*v+0] = t4.x; f[4*v+1] = t4.y;
                    f[4*v+2] = t4.z; f[4*v+3] = t4.w;
                }
            } else {
                int base = gc0a + 16 * o;
                #pragma unroll
                for (int j = 0; j < 24; ++j)
                    f[j] = __ldg(&rowp[(base + j) & NMASK]);
            }

            // Stage A: output cols 8o+0..3 from f[1..14]
            {
                float a0=0.f,a1=0.f,a2=0.f,a3=0.f;
                float d0=0.f,d1=0.f,d2=0.f,d3=0.f;
                #pragma unroll
                for (int j = 0; j < 8; ++j) {
                    FMA_LO(f[1 + j], j, a0);  FMA_HI(f[1 + j], j, d0);
                    FMA_LO(f[3 + j], j, a1);  FMA_HI(f[3 + j], j, d1);
                    FMA_LO(f[5 + j], j, a2);  FMA_HI(f[5 + j], j, d2);
                    FMA_LO(f[7 + j], j, a3);  FMA_HI(f[7 + j], j, d3);
                }
                *(float4*)&tmp[row * TSTRIDE + 8 * o]      = make_float4(a0,a1,a2,a3);
                *(float4*)&tmp[row * TSTRIDE + 32 + 8 * o] = make_float4(d0,d1,d2,d3);
            }
            // Stage B: output cols 8o+4..7 from f[9..22]
            {
                float a0=0.f,a1=0.f,a2=0.f,a3=0.f;
                float d0=0.f,d1=0.f,d2=0.f,d3=0.f;
                #pragma unroll
                for (int j = 0; j < 8; ++j) {
                    FMA_LO(f[9  + j], j, a0);  FMA_HI(f[9  + j], j, d0);
                    FMA_LO(f[11 + j], j, a1);  FMA_HI(f[11 + j], j, d1);
                    FMA_LO(f[13 + j], j, a2);  FMA_HI(f[13 + j], j, d2);
                    FMA_LO(f[15 + j], j, a3);  FMA_HI(f[15 + j], j, d3);
                }
                *(float4*)&tmp[row * TSTRIDE + 8 * o + 4]      = make_float4(a0,a1,a2,a3);
                *(float4*)&tmp[row * TSTRIDE + 32 + 8 * o + 4] = make_float4(d0,d1,d2,d3);
            }
        }
    }
    __syncthreads();

    // ---- Phase 2: vertical filter, warp-uniform; 8 output rows/thread ----
    // warp g: arr = g&1 (A cols [0,32) or D cols [32,64)), q = g>>1 (0..3).
    // Output rows 8q..8q+7 need tmp rows 16q..16q+21 (sliding window of 22).
    {
        const int tx  = tid & 31;
        const int g   = tid >> 5;
        const int arr = g & 1;
        const int q   = g >> 1;

        float sL[8] = {0,0,0,0,0,0,0,0};
        float sH[8] = {0,0,0,0,0,0,0,0};

        const float* col = &tmp[(16 * q) * TSTRIDE + 32 * arr + tx];
        #pragma unroll
        for (int i = 0; i < 22; ++i) {
            float v = col[i * TSTRIDE];
            #pragma unroll
            for (int m = 0; m < 8; ++m) {
                int j = i - 2 * m;
                if (j >= 0 && j < 8) {
                    FMA_LO(v, j, sL[m]);
                    FMA_HI(v, j, sH[m]);
                }
            }
        }

        // arr=0 -> top half rows; arr=1 -> bottom half (+NH).
        // Vertical low-pass -> left cols; high-pass -> right cols (+NH).
        float* ob = out + (size_t)b * NN * NN + (size_t)(arr * NH) * NN;
        const int C = c0 + tx;
        #pragma unroll
        for (int m = 0; m < 8; ++m) {
            int R = r0 + 8 * q + m;
            ob[R * NN + C]      = sL[m];
            ob[R * NN + C + NH] = sH[m];
        }
    }
}

extern "C" void kernel_launch(void* const* d_in, const int* in_sizes, int n_in,
                              void* d_out, int out_size)
{
    const float* x   = (const float*)d_in[0];
    const float* bmt = (const float*)d_in[1];
    float* out = (float*)d_out;

    const int B = in_sizes[0] / (NN * NN);   // 32
    dim3 grid(NH / TC, NH / TR, B);          // (16,16,32) = 8192 CTAs
    wav2d_kernel<<<grid, 256>>>(x, bmt, out);
}

// round 11
// speedup vs baseline: 1.1217x; 1.1217x over previous
#include <cuda_runtime.h>

#define NN 1024
#define NMASK 1023
#define NH 512
#define TC 32          // subband cols per block
#define TR 32          // subband rows per block
#define HROWS 70       // halo rows: 2*32 + 6
#define TSTRIDE 72     // intermediate row stride in floats

// lo[j] = w[7-j] (index reversal, free); hi[j] = (j odd) ? w[j] : -w[j]
// (negation folded into the FFMA operand modifier, free in SASS).
#define FMA_LO(v, j, s) (s) = fmaf((v), w[7 - (j)], (s))
#define FMA_HI(v, j, s) (s) = ((j) & 1) ? fmaf((v), w[(j)], (s)) \
                                        : fmaf((v), -w[(j)], (s))

__global__ __launch_bounds__(256, 7)
void wav2d_kernel(const float* __restrict__ x,
                  const float* __restrict__ bmt,
                  float* __restrict__ out)
{
    __shared__ float tmp[HROWS * TSTRIDE];   // 20160 B

    const int tid = threadIdx.x;
    const int b  = blockIdx.z;
    const int r0 = blockIdx.y * TR;
    const int c0 = blockIdx.x * TC;

    float w[8];
    #pragma unroll
    for (int j = 0; j < 8; ++j) w[j] = __ldg(&bmt[j]);

    const float* xb = x + (size_t)b * NN * NN;
    const int gr0  = 2 * r0 - 3;   // first halo row (wrapped)
    const int gc0a = 2 * c0 - 4;   // first halo col, 16B-aligned when in-bounds

    // ---- Phase 1: horizontal filter, global -> regs -> smem ----
    // Task t (of 70*8=560): row = t>>3, quad q = t&7 -> output cols 4q..4q+3.
    // Needs 16 input floats at local cols 8q .. 8q+15 (use f[1..14]).
    const bool xint = (blockIdx.x >= 1) & (blockIdx.x <= 14);
    #pragma unroll
    for (int it = 0; it < 3; ++it) {
        int task = tid + it * 256;
        if (task < HROWS * 8) {
            int row = task >> 3;
            int q   = task & 7;
            int gr  = (gr0 + row) & NMASK;
            const float* rowp = xb + (size_t)gr * NN;

            float f[16];
            if (xint) {
                const float4* p = (const float4*)(rowp + gc0a) + 2 * q;
                float4 v0 = __ldg(p),     v1 = __ldg(p + 1);
                float4 v2 = __ldg(p + 2), v3 = __ldg(p + 3);
                f[0]=v0.x;  f[1]=v0.y;  f[2]=v0.z;  f[3]=v0.w;
                f[4]=v1.x;  f[5]=v1.y;  f[6]=v1.z;  f[7]=v1.w;
                f[8]=v2.x;  f[9]=v2.y;  f[10]=v2.z; f[11]=v2.w;
                f[12]=v3.x; f[13]=v3.y; f[14]=v3.z; f[15]=v3.w;
            } else {
                int base = gc0a + 8 * q;
                #pragma unroll
                for (int j = 0; j < 16; ++j)
                    f[j] = __ldg(&rowp[(base + j) & NMASK]);
            }

            float a0=0.f, a1=0.f, a2=0.f, a3=0.f;
            float d0=0.f, d1=0.f, d2=0.f, d3=0.f;
            #pragma unroll
            for (int j = 0; j < 8; ++j) {
                FMA_LO(f[1 + j], j, a0);  FMA_HI(f[1 + j], j, d0);
                FMA_LO(f[3 + j], j, a1);  FMA_HI(f[3 + j], j, d1);
                FMA_LO(f[5 + j], j, a2);  FMA_HI(f[5 + j], j, d2);
                FMA_LO(f[7 + j], j, a3);  FMA_HI(f[7 + j], j, d3);
            }
            *(float4*)&tmp[row * TSTRIDE + 4 * q]      = make_float4(a0, a1, a2, a3);
            *(float4*)&tmp[row * TSTRIDE + 32 + 4 * q] = make_float4(d0, d1, d2, d3);
        }
    }
    __syncthreads();

    // ---- Phase 2: vertical filter, warp-uniform; 8 output rows/thread ----
    // warp g: arr = g&1 (A cols [0,32) or D cols [32,64)), q = g>>1 (0..3).
    // Output rows 8q..8q+7 need tmp rows 16q..16q+21 (sliding window of 22).
    {
        const int tx  = tid & 31;
        const int g   = tid >> 5;
        const int arr = g & 1;
        const int q   = g >> 1;

        float sL[8] = {0,0,0,0,0,0,0,0};
        float sH[8] = {0,0,0,0,0,0,0,0};

        const float* col = &tmp[(16 * q) * TSTRIDE + 32 * arr + tx];
        #pragma unroll
        for (int i = 0; i < 22; ++i) {
            float v = col[i * TSTRIDE];
            #pragma unroll
            for (int m = 0; m < 8; ++m) {
                int j = i - 2 * m;
                if (j >= 0 && j < 8) {
                    FMA_LO(v, j, sL[m]);
                    FMA_HI(v, j, sH[m]);
                }
            }
        }

        // arr=0 -> top half rows; arr=1 -> bottom half (+NH).
        // Vertical low-pass -> left cols; high-pass -> right cols (+NH).
        float* ob = out + (size_t)b * NN * NN + (size_t)(arr * NH) * NN;
        const int C = c0 + tx;
        #pragma unroll
        for (int m = 0; m < 8; ++m) {
            int R = r0 + 8 * q + m;
            ob[R * NN + C]      = sL[m];
            ob[R * NN + C + NH] = sH[m];
        }
    }
}

extern "C" void kernel_launch(void* const* d_in, const int* in_sizes, int n_in,
                              void* d_out, int out_size)
{
    const float* x   = (const float*)d_in[0];
    const float* bmt = (const float*)d_in[1];
    float* out = (float*)d_out;

    const int B = in_sizes[0] / (NN * NN);   // 32
    dim3 grid(NH / TC, NH / TR, B);          // (16,16,32) = 8192 CTAs
    wav2d_kernel<<<grid, 256>>>(x, bmt, out);
}